// round 2
// baseline (speedup 1.0000x reference)
#include <cuda_runtime.h>

#define CC 256
#define LL 8192
#define BB 8
#define CR 64
#define GC 16
#define KK 7
#define GK 112          // G*K = 16*7
#define TILE 64
#define SX_W 72         // padded halo row width (70 used, col 1..70; center t at col 4+t)

// 64 MB scratch for normalized activations (B, C, L)
__device__ float g_outn[BB * CC * LL];

// ---------- packed f32x2 helpers (FFMA2 path: 128 FMA/cyc/SM vs 64 for FFMA-3reg) ----------
__device__ __forceinline__ unsigned long long pk2(float v) {
    unsigned long long r;
    unsigned u = __float_as_uint(v);
    asm("mov.b64 %0, {%1, %1};" : "=l"(r) : "r"(u));
    return r;
}
__device__ __forceinline__ void fma2(unsigned long long& d, unsigned long long a, unsigned long long b) {
    asm("fma.rn.f32x2 %0, %1, %2, %0;" : "+l"(d) : "l"(a), "l"(b));
}
__device__ __forceinline__ float2 up2(unsigned long long v) {
    unsigned lo, hi;
    asm("mov.b64 {%0, %1}, %2;" : "=r"(lo), "=r"(hi) : "l"(v));
    return make_float2(__uint_as_float(lo), __uint_as_float(hi));
}

// ============================================================================
// Kernel 1: fused kernel-generation + involution + PReLU + LayerNorm
// grid (L/TILE=128, B=8), 256 threads, ~208KB dynamic smem, 1 CTA/SM
// ============================================================================
#define SMEM_FLOATS (256*SX_W + GK*64 + 64*64 + GK*64 + 256*64 + 128)
#define SMEM_BYTES  (SMEM_FLOATS * 4)

extern __shared__ float smem[];

__global__ void __launch_bounds__(256, 1) front_kernel(
    const float* __restrict__ x, const float* __restrict__ w_reduce,
    const float* __restrict__ w_span, const float* __restrict__ prelu_a,
    const float* __restrict__ ln_gamma, const float* __restrict__ ln_beta)
{
    float* sx    = smem;                  // [256][72]   x halo tile
    float* sspan = sx + 256 * SX_W;       // [112][64]   w_span
    float* sh    = sspan + GK * 64;       // [64][64]    h = relu(w_reduce @ x)
    float* sker  = sh + 64 * 64;          // [112][64]   involution kernels
    float* sout  = sker + GK * 64;        // [256][64]   pre-LN activations
    float* smu   = sout + 256 * 64;       // [64]
    float* srs   = smu + 64;              // [64]

    const int tid = threadIdx.x;
    const int b   = blockIdx.y;
    const int l0  = blockIdx.x * TILE;
    const float* xb = x + (size_t)b * CC * LL;

    // ---- load x halo tile (zero-padded at sequence edges) ----
    for (int idx = tid; idx < 256 * 70; idx += 256) {
        int c = idx / 70, j = idx - c * 70;
        int l = l0 - 3 + j;
        sx[c * SX_W + 1 + j] = (l >= 0 && l < LL) ? xb[c * LL + l] : 0.f;
    }
    // ---- load w_span ----
    for (int idx = tid; idx < GK * 64; idx += 256) sspan[idx] = w_span[idx];
    __syncthreads();

    const int t4 = tid & 15;      // 16 t-groups of 4 positions
    const int q  = tid >> 4;      // 16 row-groups
    const int tb = t4 << 2;       // base t within tile

    // ---- h[r][t] = relu(sum_c w_reduce[r][c] * x[c][t]),  r in 0..63 ----
    #pragma unroll
    for (int i = 0; i < 4; i++) {
        int r = q + 16 * i;
        const float* wr = w_reduce + r * 256;
        unsigned long long acc0 = 0ull, acc1 = 0ull;
        #pragma unroll 8
        for (int c = 0; c < 256; c++) {
            unsigned long long wd = pk2(__ldg(wr + c));
            const float* p = sx + c * SX_W + 4 + tb;
            fma2(acc0, wd, *(const unsigned long long*)p);
            fma2(acc1, wd, *(const unsigned long long*)(p + 2));
        }
        float2 v0 = up2(acc0), v1 = up2(acc1);
        float* o = sh + r * 64 + tb;
        o[0] = fmaxf(v0.x, 0.f); o[1] = fmaxf(v0.y, 0.f);
        o[2] = fmaxf(v1.x, 0.f); o[3] = fmaxf(v1.y, 0.f);
    }
    __syncthreads();

    // ---- ker[k][t] = sum_r w_span[k][r] * h[r][t],  k in 0..111 ----
    #pragma unroll
    for (int i = 0; i < 7; i++) {
        int k = q + 16 * i;
        const float* wk = sspan + k * 64;
        unsigned long long acc0 = 0ull, acc1 = 0ull;
        #pragma unroll 8
        for (int r = 0; r < 64; r++) {
            unsigned long long wd = pk2(wk[r]);
            const float* p = sh + r * 64 + tb;
            fma2(acc0, wd, *(const unsigned long long*)p);
            fma2(acc1, wd, *(const unsigned long long*)(p + 2));
        }
        float2 v0 = up2(acc0), v1 = up2(acc1);
        float* o = sker + k * 64 + tb;
        o[0] = v0.x; o[1] = v0.y; o[2] = v1.x; o[3] = v1.y;
    }
    __syncthreads();

    // ---- involution (weighted window sum over K=7) + PReLU ----
    const float al = prelu_a[0];
    #pragma unroll
    for (int i = 0; i < 16; i++) {
        int c  = q + 16 * i;
        int g7 = (c >> 4) * KK;
        float a0 = 0.f, a1 = 0.f, a2 = 0.f, a3 = 0.f;
        const float* xr = sx + c * SX_W + 1 + tb;   // xr[j+k] = x[l0+tb+j + k-3]
        #pragma unroll
        for (int k = 0; k < KK; k++) {
            float4 kv = *(const float4*)(sker + (g7 + k) * 64 + tb);
            a0 += kv.x * xr[k];
            a1 += kv.y * xr[k + 1];
            a2 += kv.z * xr[k + 2];
            a3 += kv.w * xr[k + 3];
        }
        float* o = sout + c * 64 + tb;
        o[0] = a0 >= 0.f ? a0 : al * a0;
        o[1] = a1 >= 0.f ? a1 : al * a1;
        o[2] = a2 >= 0.f ? a2 : al * a2;
        o[3] = a3 >= 0.f ? a3 : al * a3;
    }
    __syncthreads();

    // ---- LayerNorm statistics over channels, per position ----
    {
        int col = tid >> 2, part = tid & 3;   // 4 threads per column
        float s = 0.f, s2 = 0.f;
        const float* p = sout + part * 64 * 64 + col;
        #pragma unroll 8
        for (int c = 0; c < 64; c++) { float v = p[c * 64]; s += v; s2 += v * v; }
        s  += __shfl_xor_sync(0xffffffffu, s, 1);
        s2 += __shfl_xor_sync(0xffffffffu, s2, 1);
        s  += __shfl_xor_sync(0xffffffffu, s, 2);
        s2 += __shfl_xor_sync(0xffffffffu, s2, 2);
        if (part == 0) {
            float mu  = s * (1.f / 256.f);
            float var = s2 * (1.f / 256.f) - mu * mu;
            smu[col] = mu;
            srs[col] = rsqrtf(var + 1e-5f);
        }
    }
    __syncthreads();

    // ---- normalize + affine, write outn to scratch ----
    float* ob = g_outn + (size_t)b * CC * LL + l0;
    for (int idx = tid; idx < 256 * 64; idx += 256) {
        int c = idx >> 6, t = idx & 63;
        float v = (sout[idx] - smu[t]) * srs[t];
        ob[c * LL + t] = v * __ldg(ln_gamma + c) + __ldg(ln_beta + c);
    }
}

// ============================================================================
// Kernel 2: fused main/skip GEMM + residual.
// out[512, 65536] = [w_main; w_skip] @ outn ; main half += x.
// Block tile 128x128, K-chunk 16, 8x8 thread tiles, packed-f32x2 accumulate.
// grid (B*L/128 = 512, 4), 256 threads.
// ============================================================================
__global__ void __launch_bounds__(256, 2) gemm_kernel(
    const float* __restrict__ x, const float* __restrict__ w_main,
    const float* __restrict__ w_skip, float* __restrict__ out)
{
    __shared__ float As[2][16][132];   // transposed W tile, padded
    __shared__ float Bs[2][16][128];   // outn tile

    const int tid = threadIdx.x;
    const int b   = blockIdx.x >> 6;          // / (L/128)
    const int l0  = (blockIdx.x & 63) << 7;   // * 128
    const int m0  = blockIdx.y << 7;
    const float* W = (m0 < 256) ? (w_main + m0 * 256) : (w_skip + (m0 - 256) * 256);
    const float* Bbase = g_outn + (size_t)b * CC * LL + l0;

    unsigned long long acc[8][4];
    #pragma unroll
    for (int i = 0; i < 8; i++)
        #pragma unroll
        for (int j = 0; j < 4; j++) acc[i][j] = 0ull;

    // ---- prologue: load k-chunk 0 into buffer 0 ----
    #pragma unroll
    for (int it = 0; it < 2; it++) {
        int v  = tid + (it << 8);
        int m  = v >> 2, k0 = (v & 3) << 2;
        float4 ra = *(const float4*)(W + m * 256 + k0);
        As[0][k0 + 0][m] = ra.x; As[0][k0 + 1][m] = ra.y;
        As[0][k0 + 2][m] = ra.z; As[0][k0 + 3][m] = ra.w;
        int k = v >> 5, n0 = (v & 31) << 2;
        *(float4*)&Bs[0][k][n0] = *(const float4*)(Bbase + (size_t)k * LL + n0);
    }
    __syncthreads();

    const int ty = tid >> 4, tx = tid & 15;

    for (int kt = 0; kt < 16; kt++) {
        const int cur = kt & 1;
        float4 ra0, ra1, rb0, rb1;
        if (kt < 15) {
            const int kc = (kt + 1) << 4;
            {
                int v = tid;
                int m = v >> 2, k0 = (v & 3) << 2;
                ra0 = *(const float4*)(W + m * 256 + kc + k0);
                int k = v >> 5, n0 = (v & 31) << 2;
                rb0 = *(const float4*)(Bbase + (size_t)(kc + k) * LL + n0);
            }
            {
                int v = tid + 256;
                int m = v >> 2, k0 = (v & 3) << 2;
                ra1 = *(const float4*)(W + m * 256 + kc + k0);
                int k = v >> 5, n0 = (v & 31) << 2;
                rb1 = *(const float4*)(Bbase + (size_t)(kc + k) * LL + n0);
            }
        }
        #pragma unroll
        for (int k = 0; k < 16; k++) {
            float4 a0 = *(const float4*)&As[cur][k][ty << 3];
            float4 a1 = *(const float4*)&As[cur][k][(ty << 3) + 4];
            const unsigned long long* bp = (const unsigned long long*)&Bs[cur][k][tx << 3];
            unsigned long long b0 = bp[0], b1 = bp[1], b2 = bp[2], b3 = bp[3];
            unsigned long long d;
            d = pk2(a0.x); fma2(acc[0][0], d, b0); fma2(acc[0][1], d, b1); fma2(acc[0][2], d, b2); fma2(acc[0][3], d, b3);
            d = pk2(a0.y); fma2(acc[1][0], d, b0); fma2(acc[1][1], d, b1); fma2(acc[1][2], d, b2); fma2(acc[1][3], d, b3);
            d = pk2(a0.z); fma2(acc[2][0], d, b0); fma2(acc[2][1], d, b1); fma2(acc[2][2], d, b2); fma2(acc[2][3], d, b3);
            d = pk2(a0.w); fma2(acc[3][0], d, b0); fma2(acc[3][1], d, b1); fma2(acc[3][2], d, b2); fma2(acc[3][3], d, b3);
            d = pk2(a1.x); fma2(acc[4][0], d, b0); fma2(acc[4][1], d, b1); fma2(acc[4][2], d, b2); fma2(acc[4][3], d, b3);
            d = pk2(a1.y); fma2(acc[5][0], d, b0); fma2(acc[5][1], d, b1); fma2(acc[5][2], d, b2); fma2(acc[5][3], d, b3);
            d = pk2(a1.z); fma2(acc[6][0], d, b0); fma2(acc[6][1], d, b1); fma2(acc[6][2], d, b2); fma2(acc[6][3], d, b3);
            d = pk2(a1.w); fma2(acc[7][0], d, b0); fma2(acc[7][1], d, b1); fma2(acc[7][2], d, b2); fma2(acc[7][3], d, b3);
        }
        if (kt < 15) {
            __syncthreads();
            const int nxt = cur ^ 1;
            {
                int v = tid;
                int m = v >> 2, k0 = (v & 3) << 2;
                As[nxt][k0 + 0][m] = ra0.x; As[nxt][k0 + 1][m] = ra0.y;
                As[nxt][k0 + 2][m] = ra0.z; As[nxt][k0 + 3][m] = ra0.w;
                int k = v >> 5, n0 = (v & 31) << 2;
                *(float4*)&Bs[nxt][k][n0] = rb0;
            }
            {
                int v = tid + 256;
                int m = v >> 2, k0 = (v & 3) << 2;
                As[nxt][k0 + 0][m] = ra1.x; As[nxt][k0 + 1][m] = ra1.y;
                As[nxt][k0 + 2][m] = ra1.z; As[nxt][k0 + 3][m] = ra1.w;
                int k = v >> 5, n0 = (v & 31) << 2;
                *(float4*)&Bs[nxt][k][n0] = rb1;
            }
            __syncthreads();
        }
    }

    // ---- epilogue: +x residual on main half, write both outputs ----
    const size_t CL = (size_t)CC * LL;
    const int n = l0 + (tx << 3);
    #pragma unroll
    for (int im = 0; im < 8; im++) {
        int m = m0 + (ty << 3) + im;
        float2 p0 = up2(acc[im][0]), p1 = up2(acc[im][1]);
        float2 p2 = up2(acc[im][2]), p3 = up2(acc[im][3]);
        float4 r0 = make_float4(p0.x, p0.y, p1.x, p1.y);
        float4 r1 = make_float4(p2.x, p2.y, p3.x, p3.y);
        float* dst;
        if (m < 256) {
            const float* xr = x + (size_t)b * CL + (size_t)m * LL + n;
            float4 x0 = *(const float4*)xr;
            float4 x1 = *(const float4*)(xr + 4);
            r0.x += x0.x; r0.y += x0.y; r0.z += x0.z; r0.w += x0.w;
            r1.x += x1.x; r1.y += x1.y; r1.z += x1.z; r1.w += x1.w;
            dst = out + (size_t)b * CL + (size_t)m * LL + n;
        } else {
            dst = out + (size_t)BB * CL + (size_t)b * CL + (size_t)(m - 256) * LL + n;
        }
        *(float4*)dst = r0;
        *(float4*)(dst + 4) = r1;
    }
}

// ============================================================================
extern "C" void kernel_launch(void* const* d_in, const int* in_sizes, int n_in,
                              void* d_out, int out_size) {
    const float* x        = (const float*)d_in[0];
    const float* w_reduce = (const float*)d_in[1];
    const float* w_span   = (const float*)d_in[2];
    const float* prelu_a  = (const float*)d_in[3];
    const float* ln_gamma = (const float*)d_in[4];
    const float* ln_beta  = (const float*)d_in[5];
    const float* w_main   = (const float*)d_in[6];
    const float* w_skip   = (const float*)d_in[7];
    float* out = (float*)d_out;

    cudaFuncSetAttribute(front_kernel, cudaFuncAttributeMaxDynamicSharedMemorySize, SMEM_BYTES);

    front_kernel<<<dim3(LL / TILE, BB), 256, SMEM_BYTES>>>(
        x, w_reduce, w_span, prelu_a, ln_gamma, ln_beta);
    gemm_kernel<<<dim3((BB * LL) / 128, 4), 256>>>(x, w_main, w_skip, out);
}